// round 2
// baseline (speedup 1.0000x reference)
#include <cuda_runtime.h>

// RX gate on qubit 5 of 12-qubit statevector, batch 4096.
// out_re[j] = c*sr[j] + s*si[j^64]
// out_im[j] = c*si[j] - s*sr[j^64]
// d_out layout: [out_re (4096*4096 floats) | out_im (4096*4096 floats)]

#define NELEM    (4096 * 4096)        // elements per array
#define NTHREADS (NELEM / 16)         // each thread: 2 float4 low + 2 float4 high

__device__ __forceinline__ float4 ldcs4(const float4* p) {
    return __ldcs(p);
}
__device__ __forceinline__ void stcs4(float4* p, float4 v) {
    __stcs(p, v);
}

__global__ void __launch_bounds__(256)
rx_gate_kernel(const float4* __restrict__ sr4,
               const float4* __restrict__ si4,
               const float*  __restrict__ theta,
               float4* __restrict__ ore4,
               float4* __restrict__ oim4)
{
    int t = blockIdx.x * blockDim.x + threadIdx.x;

    float half = 0.5f * __ldg(theta);
    float s, c;
    sincosf(half, &s, &c);

    // 128-element group = 32 float4s: low half (bit6=0) = first 16 float4s,
    // high half (bit6=1) = next 16. 8 threads per group, 2 float4s each side.
    int grp = t >> 3;
    int w   = (t & 7) << 1;
    int ilo = grp * 32 + w;      // float4 index, element bit6 = 0
    int ihi = ilo + 16;          // partner float4 (element ^ 64)

    // Front-batch all 8 loads (128 B) for max MLP.
    float4 ar0 = ldcs4(sr4 + ilo);
    float4 ar1 = ldcs4(sr4 + ilo + 1);
    float4 br0 = ldcs4(sr4 + ihi);
    float4 br1 = ldcs4(sr4 + ihi + 1);
    float4 ai0 = ldcs4(si4 + ilo);
    float4 ai1 = ldcs4(si4 + ilo + 1);
    float4 bi0 = ldcs4(si4 + ihi);
    float4 bi1 = ldcs4(si4 + ihi + 1);

    float4 v;

    // out_re low: c*ar + s*bi
    v.x = fmaf(c, ar0.x, s * bi0.x); v.y = fmaf(c, ar0.y, s * bi0.y);
    v.z = fmaf(c, ar0.z, s * bi0.z); v.w = fmaf(c, ar0.w, s * bi0.w);
    stcs4(ore4 + ilo, v);
    v.x = fmaf(c, ar1.x, s * bi1.x); v.y = fmaf(c, ar1.y, s * bi1.y);
    v.z = fmaf(c, ar1.z, s * bi1.z); v.w = fmaf(c, ar1.w, s * bi1.w);
    stcs4(ore4 + ilo + 1, v);

    // out_re high: c*br + s*ai
    v.x = fmaf(c, br0.x, s * ai0.x); v.y = fmaf(c, br0.y, s * ai0.y);
    v.z = fmaf(c, br0.z, s * ai0.z); v.w = fmaf(c, br0.w, s * ai0.w);
    stcs4(ore4 + ihi, v);
    v.x = fmaf(c, br1.x, s * ai1.x); v.y = fmaf(c, br1.y, s * ai1.y);
    v.z = fmaf(c, br1.z, s * ai1.z); v.w = fmaf(c, br1.w, s * ai1.w);
    stcs4(ore4 + ihi + 1, v);

    // out_im low: c*ai - s*br
    v.x = fmaf(c, ai0.x, -s * br0.x); v.y = fmaf(c, ai0.y, -s * br0.y);
    v.z = fmaf(c, ai0.z, -s * br0.z); v.w = fmaf(c, ai0.w, -s * br0.w);
    stcs4(oim4 + ilo, v);
    v.x = fmaf(c, ai1.x, -s * br1.x); v.y = fmaf(c, ai1.y, -s * br1.y);
    v.z = fmaf(c, ai1.z, -s * br1.z); v.w = fmaf(c, ai1.w, -s * br1.w);
    stcs4(oim4 + ilo + 1, v);

    // out_im high: c*bi - s*ar
    v.x = fmaf(c, bi0.x, -s * ar0.x); v.y = fmaf(c, bi0.y, -s * ar0.y);
    v.z = fmaf(c, bi0.z, -s * ar0.z); v.w = fmaf(c, bi0.w, -s * ar0.w);
    stcs4(oim4 + ihi, v);
    v.x = fmaf(c, bi1.x, -s * ar1.x); v.y = fmaf(c, bi1.y, -s * ar1.y);
    v.z = fmaf(c, bi1.z, -s * ar1.z); v.w = fmaf(c, bi1.w, -s * ar1.w);
    stcs4(oim4 + ihi + 1, v);
}

extern "C" void kernel_launch(void* const* d_in, const int* in_sizes, int n_in,
                              void* d_out, int out_size)
{
    const float4* sr4   = (const float4*)d_in[0];
    const float4* si4   = (const float4*)d_in[1];
    const float*  theta = (const float*)d_in[2];

    float* out   = (float*)d_out;
    float4* ore4 = (float4*)out;
    float4* oim4 = (float4*)(out + NELEM);

    const int threads = 256;
    const int blocks  = NTHREADS / threads;   // 4096, exact
    rx_gate_kernel<<<blocks, threads>>>(sr4, si4, theta, ore4, oim4);
}

// round 3
// speedup vs baseline: 1.1307x; 1.1307x over previous
#include <cuda_runtime.h>

// RX gate on qubit 5 of a 12-qubit statevector, batch 4096.
// out_re[j] = c*sr[j] + s*si[j^64]
// out_im[j] = c*si[j] - s*sr[j^64]
// d_out layout: [out_re (4096*4096 floats) | out_im (4096*4096 floats)]
//
// Layout: R1's coalesced mapping. 128-element group = 32 float4s.
// Thread t -> group t>>4, lane w = t&15. Lanes 0..15 cover the low half
// (bit6=0) contiguously; partner is +16 float4s. Every warp-level LDG/STG
// touches contiguous 256B chunks -> minimal L1tex wavefronts.

#define NELEM   (4096 * 4096)
#define NPAIRT  (NELEM / 8)     // one thread = 1 low float4 + 1 high float4

__global__ void __launch_bounds__(256)
rx_gate_kernel(const float4* __restrict__ sr4,
               const float4* __restrict__ si4,
               const float*  __restrict__ theta,
               float4* __restrict__ ore4,
               float4* __restrict__ oim4)
{
    int t = blockIdx.x * blockDim.x + threadIdx.x;

    float half = 0.5f * __ldg(theta);
    float s, c;
    sincosf(half, &s, &c);

    int grp = t >> 4;
    int w   = t & 15;
    int ilo = grp * 32 + w;    // element bit6 = 0
    int ihi = ilo + 16;        // element ^ 64

    float4 a_re = sr4[ilo];
    float4 b_re = sr4[ihi];
    float4 a_im = si4[ilo];
    float4 b_im = si4[ihi];

    float4 v;

    // out_re low: c*ar + s*bi
    v.x = fmaf(c, a_re.x, s * b_im.x);
    v.y = fmaf(c, a_re.y, s * b_im.y);
    v.z = fmaf(c, a_re.z, s * b_im.z);
    v.w = fmaf(c, a_re.w, s * b_im.w);
    __stcs(ore4 + ilo, v);

    // out_re high: c*br + s*ai
    v.x = fmaf(c, b_re.x, s * a_im.x);
    v.y = fmaf(c, b_re.y, s * a_im.y);
    v.z = fmaf(c, b_re.z, s * a_im.z);
    v.w = fmaf(c, b_re.w, s * a_im.w);
    __stcs(ore4 + ihi, v);

    // out_im low: c*ai - s*br
    v.x = fmaf(c, a_im.x, -s * b_re.x);
    v.y = fmaf(c, a_im.y, -s * b_re.y);
    v.z = fmaf(c, a_im.z, -s * b_re.z);
    v.w = fmaf(c, a_im.w, -s * b_re.w);
    __stcs(oim4 + ilo, v);

    // out_im high: c*bi - s*ar
    v.x = fmaf(c, b_im.x, -s * a_re.x);
    v.y = fmaf(c, b_im.y, -s * a_re.y);
    v.z = fmaf(c, b_im.z, -s * a_re.z);
    v.w = fmaf(c, b_im.w, -s * a_re.w);
    __stcs(oim4 + ihi, v);
}

extern "C" void kernel_launch(void* const* d_in, const int* in_sizes, int n_in,
                              void* d_out, int out_size)
{
    const float4* sr4   = (const float4*)d_in[0];
    const float4* si4   = (const float4*)d_in[1];
    const float*  theta = (const float*)d_in[2];

    float* out   = (float*)d_out;
    float4* ore4 = (float4*)out;
    float4* oim4 = (float4*)(out + NELEM);

    const int threads = 256;
    const int blocks  = NPAIRT / threads;   // 8192, exact
    rx_gate_kernel<<<blocks, threads>>>(sr4, si4, theta, ore4, oim4);
}